// round 3
// baseline (speedup 1.0000x reference)
#include <cuda_runtime.h>

// y[b,j0,j1,j2] = sum_{a1,a2,a3} x[b,a1,a2,a3] w0[a1,j0] w1[a2,j1] w2[a3,j2]
// Three identical in-smem stages per batch cube:
//   out[m*32+j] = sum_i in[i*1024+m] * w[i*32+j]
// XOR bank swizzle on the cube makes fiber reads (stride-1024), row writes
// (stride-32) and the final float4 pack all bank-conflict-free.

#define NTHREADS 1024
#define CUBE 32768   // 32*32*32 floats per batch element

typedef unsigned long long ull;

__device__ __forceinline__ ull pack2f(float a, float b) {
    ull r;
    asm("mov.b64 %0, {%1, %2};" : "=l"(r) : "f"(a), "f"(b));
    return r;
}
__device__ __forceinline__ void unpack2f(ull v, float &a, float &b) {
    asm("mov.b64 {%0, %1}, %2;" : "=f"(a), "=f"(b) : "l"(v));
}
// Packed fp32x2 FMA (sm_100+): two exact fp32 FMAs per instruction.
__device__ __forceinline__ ull fma2(ull a, ull b, ull c) {
    ull d;
    asm("fma.rn.f32x2 %0, %1, %2, %3;" : "=l"(d) : "l"(a), "l"(b), "l"(c));
    return d;
}

extern __shared__ float s_cube[];   // [32768] cube, then ull wp[3*512] packed weights

__global__ __launch_bounds__(NTHREADS, 1)
void L1_kernel(const float* __restrict__ x,
               const float* __restrict__ w0,
               const float* __restrict__ w1,
               const float* __restrict__ w2,
               float* __restrict__ out)
{
    float* cube = s_cube;
    ull* wp = reinterpret_cast<ull*>(s_cube + CUBE);

    const int t = threadIdx.x;
    const int b = blockIdx.x;

    // ---- pack weights: wp[stage*512 + j*16 + i2] = {w[2*i2][j], w[2*i2+1][j]}
    // j-major so each j's 16 packs are contiguous -> LDS.128 in the hot loop.
    {
        const float* ws[3] = {w0, w1, w2};
        #pragma unroll
        for (int e = t; e < 1536; e += NTHREADS) {
            int stage = e >> 9;
            int r     = e & 511;
            int j     = r >> 4;
            int i2    = r & 15;
            const float* w = ws[stage];
            wp[e] = pack2f(w[(2 * i2) * 32 + j], w[(2 * i2 + 1) * 32 + j]);
        }
    }

    // Swizzle helpers:
    //  fiber read  L = i*1024 + t  -> phys = i*1024 + (t ^ ((t>>5)&31))
    //  row write   L = t*32 + j    -> phys = t*32 + (j ^ (t&31))
    const int t2    = t ^ ((t >> 5) & 31);
    const int k2    = t & 31;
    const int wbase = t * 32;

    ull v[16];

    // ================= stage 1: fibers straight from gmem =================
    {
        const float* xg = x + (size_t)b * CUBE;
        #pragma unroll
        for (int i2 = 0; i2 < 16; i2++) {
            float a = xg[(2 * i2)     * 1024 + t];
            float c = xg[(2 * i2 + 1) * 1024 + t];
            v[i2] = pack2f(a, c);
        }
        __syncthreads();   // wp ready (no smem cube reads before this point)
        #pragma unroll
        for (int j = 0; j < 32; j++) {
            const ulonglong2* wj =
                reinterpret_cast<const ulonglong2*>(wp + j * 16);
            ull acc = 0ull;  // (+0.0f, +0.0f)
            #pragma unroll
            for (int q = 0; q < 8; q++) {
                ulonglong2 wv = wj[q];               // LDS.128, warp-broadcast
                acc = fma2(v[2 * q],     wv.x, acc);
                acc = fma2(v[2 * q + 1], wv.y, acc);
            }
            float lo, hi; unpack2f(acc, lo, hi);
            cube[wbase + (j ^ k2)] = lo + hi;
        }
    }

    // ================= stages 2 and 3: in-place in smem =================
    #pragma unroll
    for (int stage = 1; stage < 3; stage++) {
        __syncthreads();   // all writes of previous stage visible
        #pragma unroll
        for (int i2 = 0; i2 < 16; i2++) {
            float a = cube[(2 * i2)     * 1024 + t2];
            float c = cube[(2 * i2 + 1) * 1024 + t2];
            v[i2] = pack2f(a, c);
        }
        __syncthreads();   // all fiber reads done before any in-place write
        const ull* wk = wp + stage * 512;
        #pragma unroll
        for (int j = 0; j < 32; j++) {
            const ulonglong2* wj =
                reinterpret_cast<const ulonglong2*>(wk + j * 16);
            ull acc = 0ull;
            #pragma unroll
            for (int q = 0; q < 8; q++) {
                ulonglong2 wv = wj[q];
                acc = fma2(v[2 * q],     wv.x, acc);
                acc = fma2(v[2 * q + 1], wv.y, acc);
            }
            float lo, hi; unpack2f(acc, lo, hi);
            cube[wbase + (j ^ k2)] = lo + hi;
        }
    }
    __syncthreads();

    // ================= smem -> gmem, coalesced float4 =================
    float* og = out + (size_t)b * CUBE;
    #pragma unroll
    for (int k = 0; k < 8; k++) {
        int L   = k * 4096 + t * 4;
        int key = (L >> 5) & 31;          // same key for L..L+3
        float4 r;
        r.x = cube[(L + 0) ^ key];
        r.y = cube[(L + 1) ^ key];
        r.z = cube[(L + 2) ^ key];
        r.w = cube[(L + 3) ^ key];
        *reinterpret_cast<float4*>(og + L) = r;
    }
}

extern "C" void kernel_launch(void* const* d_in, const int* in_sizes, int n_in,
                              void* d_out, int out_size) {
    const float* x  = (const float*)d_in[0];
    const float* w0 = (const float*)d_in[1];
    const float* w1 = (const float*)d_in[2];
    const float* w2 = (const float*)d_in[3];
    float* out = (float*)d_out;

    int batch = in_sizes[0] / CUBE;   // 1024 for the given shapes

    size_t smem = CUBE * sizeof(float) + 3 * 512 * sizeof(ull); // 143360 B
    cudaFuncSetAttribute(L1_kernel, cudaFuncAttributeMaxDynamicSharedMemorySize, (int)smem);

    L1_kernel<<<batch, NTHREADS, smem>>>(x, w0, w1, w2, out);
}